// round 6
// baseline (speedup 1.0000x reference)
#include <cuda_runtime.h>
#include <cuda_bf16.h>
#include <mma.h>
#include <cstdint>

using namespace nvcuda;

#define SQ 2048
#define NB 8
#define EMB 1024
#define RTOT (SQ*NB)
#define G4 (4*EMB)

#define GF_GELU   1
#define GF_CSKIP  2
#define GF_KCLAMP 4

// ---------------- device scratch (static; no allocation allowed) ----------------
__device__ float g_xln  [(size_t)RTOT*EMB];
__device__ float g_G    [(size_t)RTOT*G4];
__device__ float g_rnn  [(size_t)RTOT*EMB];
__device__ float g_hmid [(size_t)RTOT*EMB];
__device__ float g_qpre [(size_t)RTOT*EMB];
__device__ float g_qsc  [(size_t)RTOT*EMB];
__device__ float g_ksc  [(size_t)RTOT*EMB];
__device__ float g_vsc  [(size_t)RTOT*EMB];
__device__ float g_vT   [(size_t)NB*EMB*SQ];
__device__ float g_scores[(size_t)NB*SQ*SQ];
__device__ float g_h2   [(size_t)RTOT*EMB];
__device__ float g_xff  [(size_t)RTOT*EMB];
__device__ float g_res  [(size_t)RTOT*EMB];
__device__ float g_bias4[G4];
__device__ float g_op   [2*EMB];
__device__ float g_qsg  [EMB];
__device__ float g_ksg  [EMB];
__device__ float g_vsg  [EMB];
__device__ float g_hbuf [NB*EMB];
__device__ int   g_bar;

__device__ __forceinline__ float sigm(float x){ return 1.0f/(1.0f + expf(-x)); }

// ---------------- prep ----------------
__global__ void prep_kernel(const float* __restrict__ bih, const float* __restrict__ bhh,
                            const float* __restrict__ qs, const float* __restrict__ ksp){
    int i = blockIdx.x*256 + threadIdx.x;
    if (i < G4) g_bias4[i] = bih[i] + bhh[i];
    if (i < EMB){ g_qsg[i] = sigm(qs[i]); g_ksg[i] = sigm(ksp[i]); g_hbuf[i] = 0.f;
                  g_hbuf[i+EMB]=0.f; g_hbuf[i+2*EMB]=0.f; g_hbuf[i+3*EMB]=0.f;
                  g_hbuf[i+4*EMB]=0.f; g_hbuf[i+5*EMB]=0.f; g_hbuf[i+6*EMB]=0.f; g_hbuf[i+7*EMB]=0.f; }
    if (i == 0) g_bar = 0;
}

__global__ void op_gemm_kernel(const float* __restrict__ vsp, const float* __restrict__ opW,
                               const float* __restrict__ opb){
    __shared__ float vo[EMB];
    int tid = threadIdx.x;
    for (int i = tid; i < EMB; i += 256) vo[i] = sigm(vsp[i]);
    __syncthreads();
    int j = blockIdx.x*256 + tid;
    float acc = 0.f;
    const float* w = opW + (size_t)j*EMB;
    for (int e = 0; e < EMB; e += 4){
        float4 wv = *(const float4*)(w + e);
        acc += wv.x*vo[e] + wv.y*vo[e+1] + wv.z*vo[e+2] + wv.w*vo[e+3];
    }
    g_op[j] = acc + opb[j];
}

__global__ void vsg_kernel(){
    int i = blockIdx.x*256 + threadIdx.x;
    if (i < EMB) g_vsg[i] = sigm(g_op[EMB + i]) * tanhf(g_op[i]);
}

// ---------------- block reduction helpers ----------------
__device__ __forceinline__ float bsum(float v, float* buf){
    #pragma unroll
    for (int o = 16; o; o >>= 1) v += __shfl_xor_sync(0xffffffffu, v, o);
    int w = threadIdx.x >> 5;
    if ((threadIdx.x & 31) == 0) buf[w] = v;
    __syncthreads();
    if (threadIdx.x == 0){ float s = 0.f; for (int i = 0; i < 8; i++) s += buf[i]; buf[0] = s; }
    __syncthreads();
    float r = buf[0];
    __syncthreads();
    return r;
}
__device__ __forceinline__ float bmax(float v, float* buf){
    #pragma unroll
    for (int o = 16; o; o >>= 1) v = fmaxf(v, __shfl_xor_sync(0xffffffffu, v, o));
    int w = threadIdx.x >> 5;
    if ((threadIdx.x & 31) == 0) buf[w] = v;
    __syncthreads();
    if (threadIdx.x == 0){ float s = buf[0]; for (int i = 1; i < 8; i++) s = fmaxf(s, buf[i]); buf[0] = s; }
    __syncthreads();
    float r = buf[0];
    __syncthreads();
    return r;
}

// ---------------- layer norm: up to 3 outputs share stats; optional elementwise scale ----------------
__global__ void __launch_bounds__(256) ln_kernel(const float* __restrict__ in,
    float* o1, const float* g1, const float* b1, const float* s1,
    float* o2, const float* g2, const float* b2, const float* s2,
    float* o3, const float* g3, const float* b3, const float* s3){
    __shared__ float buf[8];
    size_t row = blockIdx.x;
    int tid = threadIdx.x, e = tid*4;
    const float* rp = in + row*EMB;
    float4 x = *(const float4*)(rp + e);
    float m = bsum(x.x + x.y + x.z + x.w, buf) * (1.f/EMB);
    float d0 = x.x - m, d1 = x.y - m, d2 = x.z - m, d3 = x.w - m;
    float v = bsum(d0*d0 + d1*d1 + d2*d2 + d3*d3, buf) * (1.f/EMB);
    float rstd = rsqrtf(v + 1e-12f);
    #define EMIT(o,g,b,s) if (o){ \
        float4 gv = *(const float4*)((g)+e); float4 bv = *(const float4*)((b)+e); \
        float4 y; y.x = d0*rstd*gv.x + bv.x; y.y = d1*rstd*gv.y + bv.y; \
        y.z = d2*rstd*gv.z + bv.z; y.w = d3*rstd*gv.w + bv.w; \
        if (s){ float4 sv = *(const float4*)((s)+e); y.x*=sv.x; y.y*=sv.y; y.z*=sv.z; y.w*=sv.w; } \
        *(float4*)((o) + row*EMB + e) = y; }
    EMIT(o1,g1,b1,s1); EMIT(o2,g2,b2,s2); EMIT(o3,g3,b3,s3);
    #undef EMIT
}

// ---------------- causal softmax in place; zero-fill to 128 boundary ----------------
__global__ void __launch_bounds__(256) softmax_kernel(float* __restrict__ scores){
    __shared__ float buf[8];
    int blk = blockIdx.x;
    int s = blk & (SQ-1);
    float* row = scores + (size_t)blk*SQ;
    int n = s + 1;
    int fill = ((s >> 7) + 1) << 7;
    float mx = -1e30f;
    for (int k = threadIdx.x; k < n; k += 256) mx = fmaxf(mx, row[k]);
    mx = bmax(mx, buf);
    float sm = 0.f;
    for (int k = threadIdx.x; k < n; k += 256) sm += expf(row[k] - mx);
    sm = bsum(sm, buf);
    float inv = 1.f/sm;
    for (int k = threadIdx.x; k < fill; k += 256)
        row[k] = (k < n) ? expf(row[k] - mx) * inv : 0.f;
}

// ---------------- v transpose: [s][b][e] -> [b][e][s] ----------------
__global__ void transpose_v(const float* __restrict__ vsc, float* __restrict__ vT){
    __shared__ float t[32][33];
    int b = blockIdx.z;
    int e0 = blockIdx.x*32, s0 = blockIdx.y*32;
    int x = threadIdx.x, y0 = threadIdx.y;
    for (int yy = y0; yy < 32; yy += 8)
        t[yy][x] = vsc[((size_t)(s0+yy)*NB + b)*EMB + e0 + x];
    __syncthreads();
    for (int yy = y0; yy < 32; yy += 8)
        vT[(size_t)b*EMB*SQ + (size_t)(e0+yy)*SQ + s0 + x] = t[x][yy];
}

// ---------------- generic split-bf16 wmma GEMM: C = alpha*(A@B^T)[+bias][gelu][+add] ----------------
__device__ __forceinline__ void cvt_store4(float4 v, __nv_bfloat16* hp, __nv_bfloat16* lp){
    __nv_bfloat16 h0=__float2bfloat16(v.x), h1=__float2bfloat16(v.y);
    __nv_bfloat16 h2=__float2bfloat16(v.z), h3=__float2bfloat16(v.w);
    __nv_bfloat16 l0=__float2bfloat16(v.x-__bfloat162float(h0));
    __nv_bfloat16 l1=__float2bfloat16(v.y-__bfloat162float(h1));
    __nv_bfloat16 l2=__float2bfloat16(v.z-__bfloat162float(h2));
    __nv_bfloat16 l3=__float2bfloat16(v.w-__bfloat162float(h3));
    *(__nv_bfloat162*)(hp)   = __halves2bfloat162(h0,h1);
    *(__nv_bfloat162*)(hp+2) = __halves2bfloat162(h2,h3);
    *(__nv_bfloat162*)(lp)   = __halves2bfloat162(l0,l1);
    *(__nv_bfloat162*)(lp+2) = __halves2bfloat162(l2,l3);
}

__global__ void __launch_bounds__(256) gemm_kernel(
    const float* __restrict__ A, long long lda, long long sAz,
    const float* __restrict__ B, long long ldb, long long sBz,
    float* __restrict__ C, long long ldc, long long sCz,
    int M, int N, int K,
    const float* __restrict__ bias, const float* __restrict__ addp,
    long long ldadd, long long sAddz, float alpha, int flags){
    extern __shared__ char smraw[];
    __nv_bfloat16* AS = (__nv_bfloat16*)smraw;   // hi A: 2 stages x 128 x 40
    __nv_bfloat16* BS = AS + 20480;              // hi B: 2 stages x 64 x 40

    int m0 = blockIdx.y*128, n0 = blockIdx.x*64;
    if ((flags & GF_CSKIP) && n0 > m0 + 127) return;
    int Keff = (flags & GF_KCLAMP) ? min(K, m0 + 128) : K;
    int nkt = Keff >> 5;

    A += (size_t)blockIdx.z * sAz;
    B += (size_t)blockIdx.z * sBz;
    C += (size_t)blockIdx.z * sCz;
    if (addp) addp += (size_t)blockIdx.z * sAddz;

    int tid = threadIdx.x;
    int warpId = tid >> 5, lane = tid & 31;
    int wm = warpId >> 1, wn = warpId & 1;

    wmma::fragment<wmma::accumulator,16,16,16,float> acc[2][2];
    #pragma unroll
    for (int i=0;i<2;i++)
        #pragma unroll
        for (int j=0;j<2;j++) wmma::fill_fragment(acc[i][j], 0.f);

    float4 av[4], bv[2];
    auto loadg = [&](int kt){
        int k0 = kt << 5;
        #pragma unroll
        for (int i=0;i<4;i++){ int idx = tid + i*256; int r = idx>>3, c4 = idx&7;
            av[i] = *(const float4*)(A + (size_t)(m0+r)*lda + k0 + c4*4); }
        #pragma unroll
        for (int i=0;i<2;i++){ int idx = tid + i*256; int r = idx>>3, c4 = idx&7;
            bv[i] = *(const float4*)(B + (size_t)(n0+r)*ldb + k0 + c4*4); }
    };
    auto stos = [&](int s){
        #pragma unroll
        for (int i=0;i<4;i++){ int idx = tid + i*256; int r = idx>>3, c = (idx&7)*4;
            cvt_store4(av[i], AS + s*5120 + r*40 + c, AS + 10240 + s*5120 + r*40 + c); }
        #pragma unroll
        for (int i=0;i<2;i++){ int idx = tid + i*256; int r = idx>>3, c = (idx&7)*4;
            cvt_store4(bv[i], BS + s*2560 + r*40 + c, BS + 5120 + s*2560 + r*40 + c); }
    };

    loadg(0); stos(0);
    __syncthreads();
    for (int kt = 0; kt < nkt; ++kt){
        if (kt + 1 < nkt) loadg(kt+1);
        int s = kt & 1;
        #pragma unroll
        for (int ks = 0; ks < 2; ++ks){
            wmma::fragment<wmma::matrix_a,16,16,16,__nv_bfloat16,wmma::row_major> ah[2], al[2];
            wmma::fragment<wmma::matrix_b,16,16,16,__nv_bfloat16,wmma::col_major> bh[2], bl[2];
            #pragma unroll
            for (int im=0;im<2;im++){
                const __nv_bfloat16* p = AS + s*5120 + (wm*32+im*16)*40 + ks*16;
                wmma::load_matrix_sync(ah[im], p, 40);
                wmma::load_matrix_sync(al[im], p + 10240, 40);
            }
            #pragma unroll
            for (int in=0;in<2;in++){
                const __nv_bfloat16* p = BS + s*2560 + (wn*32+in*16)*40 + ks*16;
                wmma::load_matrix_sync(bh[in], p, 40);
                wmma::load_matrix_sync(bl[in], p + 5120, 40);
            }
            #pragma unroll
            for (int im=0;im<2;im++)
                #pragma unroll
                for (int in=0;in<2;in++){
                    wmma::mma_sync(acc[im][in], ah[im], bh[in], acc[im][in]);
                    wmma::mma_sync(acc[im][in], ah[im], bl[in], acc[im][in]);
                    wmma::mma_sync(acc[im][in], al[im], bh[in], acc[im][in]);
                }
        }
        if (kt + 1 < nkt){ stos((kt+1)&1); __syncthreads(); }
    }

    __syncthreads();
    float* stg = (float*)smraw + warpId*(32*36);
    #pragma unroll
    for (int im=0;im<2;im++)
        #pragma unroll
        for (int in=0;in<2;in++)
            wmma::store_matrix_sync(stg + im*16*36 + in*16, acc[im][in], 36, wmma::mem_row_major);
    __syncwarp();
    #pragma unroll 4
    for (int i = 0; i < 32; i++){
        float v = stg[i*36 + lane] * alpha;
        int grow = m0 + wm*32 + i, gcol = n0 + wn*32 + lane;
        if (bias) v += __ldg(bias + gcol);
        if (flags & GF_GELU) v = v * (1.f/(1.f + expf(-1.702f*v)));
        if (addp) v += addp[(size_t)grow*ldadd + gcol];
        C[(size_t)grow*ldc + gcol] = v;
    }
}

// ---------------- persistent LSTM: 128 blocks x 256 threads ----------------
union __align__(16) F4U { float4 f; unsigned long long u[2]; };
union U64F2 { unsigned long long u; float2 f; };
__device__ __forceinline__ void ffma2(unsigned long long& acc, unsigned long long a, unsigned long long b){
    asm("fma.rn.f32x2 %0, %1, %2, %0;" : "+l"(acc) : "l"(a), "l"(b));
}

#define WSTR 1044
#define HSTR 1036
#define LSTM_SMEM ((32*WSTR + 8*HSTR + 256)*4)

__global__ void __launch_bounds__(256,1) lstm_kernel(const float* __restrict__ Whh){
    extern __shared__ float sm[];
    float* wsm = sm;                 // [32][WSTR]
    float* hsm = sm + 32*WSTR;       // [8][HSTR]
    float* red = hsm + 8*HSTR;       // [32][8]

    int tid = threadIdx.x;
    int c0 = blockIdx.x*8;
    int r = tid >> 3, b = tid & 7;   // dot mapping: 32 rows x 8 batches

    // load Whh slice: slice row r = gate*8+j  <->  global row gate*1024 + c0 + j
    for (int idx = tid; idx < 32*256; idx += 256){
        int rr = idx >> 8, k4 = idx & 255;
        int gate = rr >> 3, j = rr & 7;
        *(float4*)(wsm + rr*WSTR + k4*4) =
            *(const float4*)(Whh + ((size_t)(gate*1024 + c0 + j))*1024 + k4*4);
    }

    float cst = 0.f;                 // cell state (tid<64 threads own it)
    int uj = tid >> 3, ub = tid & 7; // update mapping for tid<64

    const float* wp = wsm + r*WSTR;
    const float* hp = hsm + b*HSTR;

    for (int t = 0; t < SQ; ++t){
        // prefetch G[t] for update threads
        float gi=0.f, gf=0.f, gg=0.f, go=0.f;
        if (tid < 64){
            const float* Gp = g_G + ((size_t)t*NB + ub)*G4 + c0 + uj;
            gi = __ldcs(Gp); gf = __ldcs(Gp+1024); gg = __ldcs(Gp+2048); go = __ldcs(Gp+3072);
        }
        // load h into smem (coherent via L2)
        for (int idx = tid; idx < 2048; idx += 256){
            int hb = idx >> 8, k4 = idx & 255;
            float4 hv = __ldcg((const float4*)(g_hbuf + hb*EMB + k4*4));
            *(float4*)(hsm + hb*HSTR + k4*4) = hv;
        }
        __syncthreads();

        // dot: row r x batch b, k packed in f32x2 lanes
        U64F2 acc; acc.f = make_float2(0.f, 0.f);
        #pragma unroll 4
        for (int k = 0; k < 1024; k += 4){
            F4U wv = *(const F4U*)(wp + k);
            F4U hv = *(const F4U*)(hp + k);
            ffma2(acc.u, wv.u[0], hv.u[0]);
            ffma2(acc.u, wv.u[1], hv.u[1]);
        }
        red[r*8 + b] = acc.f.x + acc.f.y;
        __syncthreads();

        if (tid < 64){
            float xi = red[(uj     )*8 + ub] + gi;
            float xf = red[(8 + uj )*8 + ub] + gf;
            float xg = red[(16 + uj)*8 + ub] + gg;
            float xo = red[(24 + uj)*8 + ub] + go;
            cst = sigm(xf)*cst + sigm(xi)*tanhf(xg);
            float hv = sigm(xo)*tanhf(cst);
            __stcg(g_hbuf + ub*EMB + c0 + uj, hv);
            g_rnn[(size_t)t*(NB*EMB) + ub*EMB + c0 + uj] = hv;
        }
        __syncthreads();
        if (tid == 0){
            __threadfence();
            atomicAdd(&g_bar, 1);
            int target = 128*(t+1);
            while (*((volatile int*)&g_bar) < target) {}
            __threadfence();
        }
        __syncthreads();
    }
}

// ---------------- host launch ----------------
extern "C" void kernel_launch(void* const* d_in, const int* in_sizes, int n_in,
                              void* d_out, int out_size){
    const float* inputs   = (const float*)d_in[0];
    const float* Wih      = (const float*)d_in[3];
    const float* Whh      = (const float*)d_in[4];
    const float* bih      = (const float*)d_in[5];
    const float* bhh      = (const float*)d_in[6];
    const float* lnstart_g=(const float*)d_in[7],  *lnstart_b=(const float*)d_in[8];
    const float* lnmem_g  =(const float*)d_in[9],  *lnmem_b  =(const float*)d_in[10];
    const float* lnmid_g  =(const float*)d_in[11], *lnmid_b  =(const float*)d_in[12];
    const float* lnff_g   =(const float*)d_in[13], *lnff_b   =(const float*)d_in[14];
    const float* lnxff_g  =(const float*)d_in[15], *lnxff_b  =(const float*)d_in[16];
    const float* qln_g    =(const float*)d_in[17], *qln_b    =(const float*)d_in[18];
    const float* qs       =(const float*)d_in[19], *ksp      =(const float*)d_in[20];
    const float* vsp      =(const float*)d_in[21];
    const float* opW      =(const float*)d_in[22], *opb      =(const float*)d_in[23];
    const float* qlW      =(const float*)d_in[24], *qlb      =(const float*)d_in[25];
    const float* boomW    =(const float*)d_in[26], *boomb    =(const float*)d_in[27];
    float* out = (float*)d_out;

    cudaFuncSetAttribute(gemm_kernel, cudaFuncAttributeMaxDynamicSharedMemorySize, 61440);
    cudaFuncSetAttribute(lstm_kernel, cudaFuncAttributeMaxDynamicSharedMemorySize, LSTM_SMEM);

    float *p_xln,*p_G,*p_rnn,*p_hmid,*p_qpre,*p_qsc,*p_ksc,*p_vsc,*p_vT,*p_scores,*p_h2,*p_xff,*p_res;
    float *p_bias4,*p_qsg,*p_ksg,*p_vsg;
    cudaGetSymbolAddress((void**)&p_xln, g_xln);
    cudaGetSymbolAddress((void**)&p_G, g_G);
    cudaGetSymbolAddress((void**)&p_rnn, g_rnn);
    cudaGetSymbolAddress((void**)&p_hmid, g_hmid);
    cudaGetSymbolAddress((void**)&p_qpre, g_qpre);
    cudaGetSymbolAddress((void**)&p_qsc, g_qsc);
    cudaGetSymbolAddress((void**)&p_ksc, g_ksc);
    cudaGetSymbolAddress((void**)&p_vsc, g_vsc);
    cudaGetSymbolAddress((void**)&p_vT, g_vT);
    cudaGetSymbolAddress((void**)&p_scores, g_scores);
    cudaGetSymbolAddress((void**)&p_h2, g_h2);
    cudaGetSymbolAddress((void**)&p_xff, g_xff);
    cudaGetSymbolAddress((void**)&p_res, g_res);
    cudaGetSymbolAddress((void**)&p_bias4, g_bias4);
    cudaGetSymbolAddress((void**)&p_qsg, g_qsg);
    cudaGetSymbolAddress((void**)&p_ksg, g_ksg);
    cudaGetSymbolAddress((void**)&p_vsg, g_vsg);

    prep_kernel<<<16,256>>>(bih, bhh, qs, ksp);
    op_gemm_kernel<<<8,256>>>(vsp, opW, opb);
    vsg_kernel<<<4,256>>>();

    // ln(inputs) -> xln
    ln_kernel<<<RTOT,256>>>(inputs, p_xln, lnstart_g, lnstart_b, nullptr,
                            nullptr,nullptr,nullptr,nullptr, nullptr,nullptr,nullptr,nullptr);
    // G = xln @ Wih^T + (bih+bhh)
    gemm_kernel<<<dim3(64,128,1),256,61440>>>(p_xln,EMB,0, Wih,EMB,0, p_G,G4,0,
        RTOT,G4,EMB, p_bias4, nullptr,0,0, 1.f, 0);
    // LSTM recurrence
    lstm_kernel<<<128,256,LSTM_SMEM>>>(Whh);
    // ln(rnn) -> hmid (lnmid), ksc (lnmem * ksg), vsc (lnmem * vsg)
    ln_kernel<<<RTOT,256>>>(p_rnn, p_hmid, lnmid_g, lnmid_b, nullptr,
                            p_ksc, lnmem_g, lnmem_b, p_ksg,
                            p_vsc, lnmem_g, lnmem_b, p_vsg);
    // qpre = hmid @ qlW^T + qlb
    gemm_kernel<<<dim3(16,128,1),256,61440>>>(p_hmid,EMB,0, qlW,EMB,0, p_qpre,EMB,0,
        RTOT,EMB,EMB, qlb, nullptr,0,0, 1.f, 0);
    // ln(qpre) -> qsc (qln * qsg)
    ln_kernel<<<RTOT,256>>>(p_qpre, p_qsc, qln_g, qln_b, p_qsg,
                            nullptr,nullptr,nullptr,nullptr, nullptr,nullptr,nullptr,nullptr);
    // scores[b] = qsc @ ksc^T / 32  (causal tile skip)
    gemm_kernel<<<dim3(32,16,8),256,61440>>>(p_qsc,NB*EMB,EMB, p_ksc,NB*EMB,EMB,
        p_scores,SQ,(long long)SQ*SQ, SQ,SQ,EMB, nullptr, nullptr,0,0, 0.03125f, GF_CSKIP);
    // causal softmax
    softmax_kernel<<<RTOT,256>>>(p_scores);
    // v transpose [s][b][e] -> [b][e][s]
    transpose_v<<<dim3(32,64,8),dim3(32,8)>>>(p_vsc, p_vT);
    // h2 = w @ vT^T + hmid  (causal K clamp)
    gemm_kernel<<<dim3(16,16,8),256,61440>>>(p_scores,SQ,(long long)SQ*SQ, p_vT,SQ,(long long)EMB*SQ,
        p_h2,NB*EMB,EMB, SQ,EMB,SQ, nullptr, p_hmid,NB*EMB,EMB, 1.f, GF_KCLAMP);
    // ln(h2) -> xff (lnxff), res (lnff)
    ln_kernel<<<RTOT,256>>>(p_h2, p_xff, lnxff_g, lnxff_b, nullptr,
                            p_res, lnff_g, lnff_b, nullptr, nullptr,nullptr,nullptr,nullptr);
    // out = gelu(xff @ boomW^T + boomb) + res
    gemm_kernel<<<dim3(16,128,1),256,61440>>>(p_xff,EMB,0, boomW,EMB,0, out,EMB,0,
        RTOT,EMB,EMB, boomb, p_res,EMB,0, 1.f, GF_GELU);
}